// round 2
// baseline (speedup 1.0000x reference)
#include <cuda_runtime.h>
#include <cstdint>
#include <cstddef>

// NOTE: harness PTX target is base sm_103 (no 'a') — tcgen05/TMEM are ptxas-rejected.
// This kernel uses the sm_80-compatible tensor path: mma.sync tf32 + cp.async.

// ---------------- problem constants ----------------
#define N_TOK   16384
#define F_DIM   1024
#define B_DIM   512
#define TILE_M  128          // tokens per CTA
#define TILE_F  64           // output features per CTA
#define GCOLS   256          // 4 gates * TILE_F gemm columns
#define KC      32           // K elements per chunk (128B rows)
#define NCHUNK  48           // 1536 / 32
#define THREADS 256

// ---------------- smem layout ----------------
#define ABYTES      (TILE_M * KC * 4)          // 16384
#define BBYTES      (GCOLS * KC * 4)           // 32768
#define STAGE_BYTES (ABYTES + BBYTES)          // 49152 (x2 stages = 98304)
#define GSM_PITCH   68                         // epilogue gate tile pitch (floats)
#define GSM_BYTES   (4 * 128 * GSM_PITCH * 4)  // 139264 (union with stage bufs)
#define SM_BIAS     GSM_BYTES
#define SMEM_TOTAL  (GSM_BYTES + 256 * 4)      // 140288

static_assert(2 * STAGE_BYTES <= GSM_BYTES, "stage/epilogue union");
static_assert(SMEM_TOTAL <= 227 * 1024, "smem cap");

// ---------------- helpers ----------------
static __device__ __forceinline__ uint32_t smem_u32(const void* p) {
    uint32_t a;
    asm("{ .reg .u64 t; cvta.to.shared.u64 t, %1; cvt.u32.u64 %0, t; }" : "=r"(a) : "l"(p));
    return a;
}

static __device__ __forceinline__ void cp16(uint32_t dst, const void* src) {
    asm volatile("cp.async.cg.shared.global [%0], [%1], 16;" :: "r"(dst), "l"(src) : "memory");
}

static __device__ __forceinline__ uint32_t f2tf32(float f) {
    uint32_t r;
    asm("cvt.rna.tf32.f32 %0, %1;" : "=r"(r) : "f"(f));
    return r;
}

static __device__ __forceinline__ void mma_tf32(float* c, const uint32_t* a, const uint32_t* b) {
    asm volatile(
        "mma.sync.aligned.m16n8k8.row.col.f32.tf32.tf32.f32 "
        "{%0,%1,%2,%3}, {%4,%5,%6,%7}, {%8,%9}, {%0,%1,%2,%3};"
        : "+f"(c[0]), "+f"(c[1]), "+f"(c[2]), "+f"(c[3])
        : "r"(a[0]), "r"(a[1]), "r"(a[2]), "r"(a[3]), "r"(b[0]), "r"(b[1]));
}

static __device__ __forceinline__ float sigf(float x) {
    return 1.0f / (1.0f + __expf(-x));
}
static __device__ __forceinline__ float tanh_fast(float x) {
    return 2.0f / (1.0f + __expf(-2.0f * x)) - 1.0f;
}

// issue cp.async loads for one K-chunk into stage buffer (raw fp32, SW128 swizzle)
static __device__ __forceinline__ void issue_chunk(
    int chunk, int stage, uint32_t sb, int tid,
    const float* __restrict__ behavior, const float* __restrict__ h_prev,
    const float* __restrict__ Wh, const float* __restrict__ Wx,
    int m_base, int c_base) {

    const float* asrc;
    const float* wk;
    int ld;
    if (chunk < 32) {                 // K in [0,1024): h_prev @ Wh^T
        asrc = h_prev + (size_t)m_base * F_DIM + chunk * KC;
        wk   = Wh + chunk * KC;
        ld   = F_DIM;
    } else {                          // K in [1024,1536): behavior @ Wx^T
        asrc = behavior + (size_t)m_base * B_DIM + (chunk - 32) * KC;
        wk   = Wx + (chunk - 32) * KC;
        ld   = B_DIM;
    }

    const uint32_t abase = sb + (uint32_t)stage * STAGE_BYTES;
#pragma unroll
    for (int i = 0; i < 4; ++i) {     // A: 128 rows x 128B
        int idx = tid + i * THREADS;  // 1024 float4 units
        int row = idx >> 3, u = idx & 7;
        cp16(abase + row * 128 + (uint32_t)((u ^ (row & 7)) << 4),
             asrc + (size_t)row * ld + u * 4);
    }
    const uint32_t bbase = abase + ABYTES;
#pragma unroll
    for (int i = 0; i < 8; ++i) {     // B: 256 gemm-col rows x 128B
        int idx = tid + i * THREADS;  // 2048 float4 units
        int rr = idx >> 3, u = idx & 7;
        int g = rr >> 6, r = rr & 63;
        cp16(bbase + rr * 128 + (uint32_t)((u ^ (rr & 7)) << 4),
             wk + (size_t)(g * F_DIM + c_base + r) * ld + u * 4);
    }
    asm volatile("cp.async.commit_group;" ::: "memory");
}

__global__ void __launch_bounds__(THREADS, 1)
lstm_mma_kernel(float* __restrict__ out,
                const float* __restrict__ behavior,
                const float* __restrict__ h_prev,
                const float* __restrict__ c_prev,
                const float* __restrict__ Wh,
                const float* __restrict__ Wx,
                const float* __restrict__ bias) {
    extern __shared__ char smem[];
    const uint32_t sb = smem_u32(smem);
    const int tid = threadIdx.x;
    const int lane = tid & 31;
    const int wid = tid >> 5;
    const int warp_m = wid & 1;        // token half (0/1)
    const int warp_n = wid >> 1;       // gate index (0..3), 64 gemm-cols each
    const int la = lane >> 2;          // 0..7
    const int lk = lane & 3;           // 0..3

    const int f_tile = blockIdx.x & 15;
    const int m_tile = blockIdx.x >> 4;
    const int m_base = m_tile * TILE_M;
    const int c_base = f_tile * TILE_F;

    // bias: 4 gates x 64 feats -> smem (survives mainloop; lives past stage bufs)
    float* bias_s = reinterpret_cast<float*>(smem + SM_BIAS);
    if (tid < 256) bias_s[tid] = bias[(tid >> 6) * F_DIM + c_base + (tid & 63)];

    float acc[4][8][4];
#pragma unroll
    for (int mt = 0; mt < 4; ++mt)
#pragma unroll
        for (int nt = 0; nt < 8; ++nt)
#pragma unroll
            for (int j = 0; j < 4; ++j) acc[mt][nt][j] = 0.0f;

    // prologue
    issue_chunk(0, 0, sb, tid, behavior, h_prev, Wh, Wx, m_base, c_base);

    for (int ch = 0; ch < NCHUNK; ++ch) {
        if (ch + 1 < NCHUNK) {
            issue_chunk(ch + 1, (ch + 1) & 1, sb, tid, behavior, h_prev, Wh, Wx, m_base, c_base);
            asm volatile("cp.async.wait_group 1;" ::: "memory");
        } else {
            asm volatile("cp.async.wait_group 0;" ::: "memory");
        }
        __syncthreads();

        const char* abase = smem + (size_t)(ch & 1) * STAGE_BYTES;
        const char* bbase = abase + ABYTES;

#pragma unroll
        for (int ks = 0; ks < 4; ++ks) {
            // A fragments: 4 m-tiles x 4 regs
            uint32_t af[4][4];
#pragma unroll
            for (int mt = 0; mt < 4; ++mt) {
                const int r1 = warp_m * 64 + mt * 16 + la;
                const int r2 = r1 + 8;
                af[mt][0] = f2tf32(*(const float*)(abase + r1 * 128 + (((2 * ks + 0) ^ (r1 & 7)) << 4) + lk * 4));
                af[mt][1] = f2tf32(*(const float*)(abase + r2 * 128 + (((2 * ks + 0) ^ (r2 & 7)) << 4) + lk * 4));
                af[mt][2] = f2tf32(*(const float*)(abase + r1 * 128 + (((2 * ks + 1) ^ (r1 & 7)) << 4) + lk * 4));
                af[mt][3] = f2tf32(*(const float*)(abase + r2 * 128 + (((2 * ks + 1) ^ (r2 & 7)) << 4) + lk * 4));
            }
            // B fragments: 8 n-tiles x 2 regs
            uint32_t bf[8][2];
#pragma unroll
            for (int nt = 0; nt < 8; ++nt) {
                const int rn = warp_n * 64 + nt * 8 + la;
                bf[nt][0] = f2tf32(*(const float*)(bbase + rn * 128 + (((2 * ks + 0) ^ (rn & 7)) << 4) + lk * 4));
                bf[nt][1] = f2tf32(*(const float*)(bbase + rn * 128 + (((2 * ks + 1) ^ (rn & 7)) << 4) + lk * 4));
            }
#pragma unroll
            for (int mt = 0; mt < 4; ++mt)
#pragma unroll
                for (int nt = 0; nt < 8; ++nt)
                    mma_tf32(acc[mt][nt], af[mt], bf[nt]);
        }
        __syncthreads();   // all reads of this stage done before it is overwritten
    }

    // ---- epilogue: dump 4 gate tiles (128 x 64 each) to smem ----
    float* gsm = reinterpret_cast<float*>(smem);
#pragma unroll
    for (int mt = 0; mt < 4; ++mt) {
#pragma unroll
        for (int nt = 0; nt < 8; ++nt) {
            const int r0 = warp_m * 64 + mt * 16 + la;
            const int f0 = nt * 8 + 2 * lk;
            const size_t o = ((size_t)(warp_n * 128 + r0)) * GSM_PITCH + f0;
            gsm[o]     = acc[mt][nt][0];
            gsm[o + 1] = acc[mt][nt][1];
            gsm[o + 8 * GSM_PITCH]     = acc[mt][nt][2];
            gsm[o + 8 * GSM_PITCH + 1] = acc[mt][nt][3];
        }
    }
    __syncthreads();

    // ---- gate math + coalesced global I/O ----
    const float* cpg = c_prev + (size_t)m_base * F_DIM + c_base;
    float* og = out + (size_t)m_base * F_DIM + c_base;
#pragma unroll
    for (int i = 0; i < (TILE_M * TILE_F) / THREADS; ++i) {
        const int idx = tid + i * THREADS;
        const int row = idx >> 6;
        const int f = idx & 63;
        const float xi = gsm[((size_t)(0 * 128 + row)) * GSM_PITCH + f] + bias_s[f];
        const float xf = gsm[((size_t)(1 * 128 + row)) * GSM_PITCH + f] + bias_s[64 + f];
        const float xg = gsm[((size_t)(2 * 128 + row)) * GSM_PITCH + f] + bias_s[128 + f];
        const float xo = gsm[((size_t)(3 * 128 + row)) * GSM_PITCH + f] + bias_s[192 + f];
        const float cv = sigf(xf) * cpg[(size_t)row * F_DIM + f] + sigf(xi) * tanh_fast(xg);
        og[(size_t)row * F_DIM + f] = sigf(xo) * tanh_fast(cv);
    }
}

extern "C" void kernel_launch(void* const* d_in, const int* in_sizes, int n_in,
                              void* d_out, int out_size) {
    const float* behavior = (const float*)d_in[0];
    const float* h_prev   = (const float*)d_in[1];
    const float* c_prev   = (const float*)d_in[2];
    const float* Wh       = (const float*)d_in[3];
    const float* Wx       = (const float*)d_in[4];
    const float* bias     = (const float*)d_in[5];

    cudaFuncSetAttribute(lstm_mma_kernel,
                         cudaFuncAttributeMaxDynamicSharedMemorySize, SMEM_TOTAL);

    const int grid = (N_TOK / TILE_M) * (F_DIM / TILE_F);  // 128 * 16 = 2048
    lstm_mma_kernel<<<grid, THREADS, SMEM_TOTAL>>>(
        (float*)d_out, behavior, h_prev, c_prev, Wh, Wx, bias);
}